// round 3
// baseline (speedup 1.0000x reference)
#include <cuda_runtime.h>
#include <math.h>

#define B_ 32
#define L_ 64
#define H_ 1024
#define E_ 8
#define V_ 12000
#define OUT_ 16
#define HID_ 512
#define COMP_OFF 512                 // gauss_param occupies out[0:512]
#define LOSS_OFF (512 + 32*64*12000) // scalar at the end

// -------------------- scratch (no allocations allowed) --------------------
__device__ float  g_hid[B_ * HID_];
__device__ int2   g_sel[B_];
__device__ float2 g_gate[B_];

// -------------------- f32x2 helpers (sm_103a packed FMA) ------------------
__device__ __forceinline__ unsigned long long pack2(float x) {
    unsigned long long r;
    asm("mov.b64 %0, {%1, %1};" : "=l"(r) : "f"(x));
    return r;
}
__device__ __forceinline__ void ffma2(unsigned long long& d,
                                      unsigned long long a,
                                      unsigned long long b) {
    asm("fma.rn.f32x2 %0, %1, %2, %0;" : "+l"(d) : "l"(a), "l"(b));
}
__device__ __forceinline__ float2 unpk(unsigned long long v) {
    float2 r;
    asm("mov.b64 {%0, %1}, %2;" : "=f"(r.x), "=f"(r.y) : "l"(v));
    return r;
}

// -------------------- K1: hid = relu(q @ w1 + b1) --------------------------
__global__ void k_hid(const float* __restrict__ q,
                      const float* __restrict__ w1,
                      const float* __restrict__ b1) {
    __shared__ float qs[H_];
    int b = blockIdx.x;
    int j = blockIdx.y * 128 + threadIdx.x;
    for (int i = threadIdx.x; i < H_; i += 128) qs[i] = q[b * H_ + i];
    __syncthreads();
    float acc = b1[j];
#pragma unroll 8
    for (int i = 0; i < H_; ++i) acc = fmaf(qs[i], w1[i * HID_ + j], acc);
    g_hid[b * HID_ + j] = fmaxf(acc, 0.0f);
}

// -------- K2: logits, top-2 softmax gates, importance, moe_loss ------------
__global__ void k_gate(const float* __restrict__ w2,
                       const float* __restrict__ b2,
                       float* __restrict__ out) {
    __shared__ float w2s[HID_ * E_];
    __shared__ float lg[B_ * E_];
    __shared__ float gd[B_ * E_];
    __shared__ float imp[E_];
    int t = threadIdx.x;
    for (int i = t; i < HID_ * E_; i += 256) w2s[i] = w2[i];
    gd[t] = 0.0f;
    __syncthreads();

    {
        int b = t >> 3, e = t & 7;
        float acc = b2[e];
        const float* hb = &g_hid[b * HID_];
#pragma unroll 8
        for (int i = 0; i < HID_; ++i) acc = fmaf(hb[i], w2s[i * E_ + e], acc);
        lg[t] = acc;
    }
    __syncthreads();

    if (t < B_) {
        float v1 = -1e30f, v2 = -1e30f;
        int i1 = 0, i2 = 0;
        for (int e = 0; e < E_; ++e) {
            float v = lg[t * E_ + e];
            if (v > v1)      { v2 = v1; i2 = i1; v1 = v; i1 = e; }
            else if (v > v2) { v2 = v;  i2 = e; }
        }
        float ex = expf(v2 - v1);
        float s = 1.0f + ex;
        float g1 = 1.0f / s, g2 = ex / s;
        g_sel[t] = make_int2(i1, i2);
        g_gate[t] = make_float2(g1, g2);
        gd[t * E_ + i1] = g1;
        gd[t * E_ + i2] = g2;
    }
    __syncthreads();
    if (t < E_) {
        float s = 0.0f;
        for (int b = 0; b < B_; ++b) s += gd[b * E_ + t];
        imp[t] = s;
    }
    __syncthreads();
    if (t == 0) {
        float mean = 0.0f;
        for (int e = 0; e < E_; ++e) mean += imp[e];
        mean *= (1.0f / E_);
        float var = 0.0f;
        for (int e = 0; e < E_; ++e) { float d = imp[e] - mean; var += d * d; }
        var *= (1.0f / (E_ - 1));
        out[LOSS_OFF] = sqrtf(var) / (mean + 1e-10f) * 0.1f;
    }
}

// -------- K3: gauss_param = sigmoid(h_last . mixed_w + mixed_b) ------------
__global__ void k_gauss(const float* __restrict__ h,
                        const float* __restrict__ gw,
                        const float* __restrict__ gb,
                        float* __restrict__ out) {
    int b = blockIdx.x;
    int o = threadIdx.x >> 5;
    int l = threadIdx.x & 31;
    int2 sel = g_sel[b];
    float2 gg = g_gate[b];
    const float* hl  = h + ((size_t)b * L_ + (L_ - 1)) * H_;
    const float* w1p = gw + ((size_t)sel.x * OUT_ + o) * H_;
    const float* w2p = gw + ((size_t)sel.y * OUT_ + o) * H_;
    float a1 = 0.0f, a2 = 0.0f;
    for (int i = l; i < H_; i += 32) {
        float hv = hl[i];
        a1 = fmaf(hv, w1p[i], a1);
        a2 = fmaf(hv, w2p[i], a2);
    }
#pragma unroll
    for (int off = 16; off > 0; off >>= 1) {
        a1 += __shfl_down_sync(0xffffffff, a1, off);
        a2 += __shfl_down_sync(0xffffffff, a2, off);
    }
    if (l == 0) {
        float val = gg.x * a1 + gg.y * a2 +
                    gg.x * gb[sel.x * OUT_ + o] + gg.y * gb[sel.y * OUT_ + o];
        out[b * OUT_ + o] = 1.0f / (1.0f + expf(-val));
    }
}

// -------- K4: comp = h @ (g1 W_e1 + g2 W_e2)^T + mixed_bias ----------------
// Block tile: 64 (all L of one b) x 256 (v). Thread tile 16m x 4n, accs
// packed along m for fma.rn.f32x2. 2-expert loop inside (gate folded into
// smem store) => comp written once, coalesced, no atomics.
__global__ __launch_bounds__(256, 2)
void k_comp(const float* __restrict__ h,
            const float* __restrict__ comp_w,
            const float* __restrict__ comp_b,
            float* __restrict__ out) {
    __shared__ __align__(16) float w_s[32 * 256];
    __shared__ __align__(16) float h_s[32][64];

    int b = blockIdx.x;
    int vbase = blockIdx.y * 256;
    int t = threadIdx.x;
    int tid_n = t & 63;
    int tid_m = t >> 6;          // warp-uniform (2 warps per tid_m)
    int m0 = tid_m * 16;
    int v0 = vbase + tid_n * 4;

    int2 sel = g_sel[b];
    float2 gg = g_gate[b];

    unsigned long long acc[8][4];
#pragma unroll
    for (int i = 0; i < 8; ++i)
#pragma unroll
        for (int j = 0; j < 4; ++j) acc[i][j] = 0ull;

    const float* hb = h + (size_t)b * L_ * H_;

    for (int ei = 0; ei < 2; ++ei) {
        int e  = ei ? sel.y : sel.x;
        float g = ei ? gg.y : gg.x;
        const float* Wb = comp_w + (size_t)e * V_ * H_;

        for (int kc = 0; kc < 32; ++kc) {
            int k0 = kc * 32;
            // ---- global loads into regs (overlap with previous compute) ----
            float4 wreg[8];
            int krow = (t & 7) * 4;
#pragma unroll
            for (int it = 0; it < 8; ++it) {
                int vl = (t >> 3) + 32 * it;
                int vr = vbase + vl;
                if (vr >= V_) vr = V_ - 1;
                wreg[it] = *(const float4*)&Wb[(size_t)vr * H_ + k0 + krow];
            }
            int l = t >> 2, ko = (t & 3) * 8;
            float4 h0 = *(const float4*)&hb[(size_t)l * H_ + k0 + ko];
            float4 h1 = *(const float4*)&hb[(size_t)l * H_ + k0 + ko + 4];

            __syncthreads();
            // ---- transposed smem stores (XOR-swizzled, gate folded in) ----
#pragma unroll
            for (int it = 0; it < 8; ++it) {
                int vl = (t >> 3) + 32 * it;
                int c = vl >> 2, lig = vl & 3;
                int kk;
                kk = krow + 0; w_s[kk * 256 + ((c ^ kk) << 2) + lig] = g * wreg[it].x;
                kk = krow + 1; w_s[kk * 256 + ((c ^ kk) << 2) + lig] = g * wreg[it].y;
                kk = krow + 2; w_s[kk * 256 + ((c ^ kk) << 2) + lig] = g * wreg[it].z;
                kk = krow + 3; w_s[kk * 256 + ((c ^ kk) << 2) + lig] = g * wreg[it].w;
            }
            h_s[ko + 0][l] = h0.x; h_s[ko + 1][l] = h0.y;
            h_s[ko + 2][l] = h0.z; h_s[ko + 3][l] = h0.w;
            h_s[ko + 4][l] = h1.x; h_s[ko + 5][l] = h1.y;
            h_s[ko + 6][l] = h1.z; h_s[ko + 7][l] = h1.w;
            __syncthreads();

            // ---- inner product: 32 k-steps, 32 FFMA2 each ----
#pragma unroll 4
            for (int kk = 0; kk < 32; ++kk) {
                const ulonglong2* ap = (const ulonglong2*)&h_s[kk][m0];
                ulonglong2 a0 = ap[0], a1 = ap[1], a2 = ap[2], a3 = ap[3];
                const float4 w4 =
                    *(const float4*)&w_s[kk * 256 + ((tid_n ^ kk) << 2)];
                unsigned long long b0 = pack2(w4.x), b1 = pack2(w4.y),
                                   b2 = pack2(w4.z), b3 = pack2(w4.w);
#define FF(mi, ai)                                                           \
                ffma2(acc[mi][0], ai, b0); ffma2(acc[mi][1], ai, b1);        \
                ffma2(acc[mi][2], ai, b2); ffma2(acc[mi][3], ai, b3);
                FF(0, a0.x) FF(1, a0.y) FF(2, a1.x) FF(3, a1.y)
                FF(4, a2.x) FF(5, a2.y) FF(6, a3.x) FF(7, a3.y)
#undef FF
            }
        }
    }

    // ---- epilogue: mixed bias + store ----
    if (v0 < V_) {
        float4 cb1 = *(const float4*)&comp_b[(size_t)sel.x * V_ + v0];
        float4 cb2 = *(const float4*)&comp_b[(size_t)sel.y * V_ + v0];
        float bias0 = gg.x * cb1.x + gg.y * cb2.x;
        float bias1 = gg.x * cb1.y + gg.y * cb2.y;
        float bias2 = gg.x * cb1.z + gg.y * cb2.z;
        float bias3 = gg.x * cb1.w + gg.y * cb2.w;
        float* co = out + COMP_OFF + (size_t)b * L_ * V_;
#pragma unroll
        for (int m = 0; m < 16; ++m) {
            int mp = m >> 1, hi = m & 1;
            float2 p0 = unpk(acc[mp][0]);
            float2 p1 = unpk(acc[mp][1]);
            float2 p2 = unpk(acc[mp][2]);
            float2 p3 = unpk(acc[mp][3]);
            float4 o;
            o.x = (hi ? p0.y : p0.x) + bias0;
            o.y = (hi ? p1.y : p1.x) + bias1;
            o.z = (hi ? p2.y : p2.x) + bias2;
            o.w = (hi ? p3.y : p3.x) + bias3;
            *(float4*)&co[(size_t)(m0 + m) * V_ + v0] = o;
        }
    }
}

// ---------------------------------------------------------------------------
extern "C" void kernel_launch(void* const* d_in, const int* in_sizes, int n_in,
                              void* d_out, int out_size) {
    const float* q      = (const float*)d_in[0];
    const float* h      = (const float*)d_in[1];
    const float* gw1    = (const float*)d_in[2];
    const float* gb1    = (const float*)d_in[3];
    const float* gw2    = (const float*)d_in[4];
    const float* gb2    = (const float*)d_in[5];
    const float* gaussw = (const float*)d_in[6];
    const float* gaussb = (const float*)d_in[7];
    const float* compw  = (const float*)d_in[8];
    const float* compb  = (const float*)d_in[9];
    float* out = (float*)d_out;

    k_hid<<<dim3(B_, 4), 128>>>(q, gw1, gb1);
    k_gate<<<1, 256>>>(gw2, gb2, out);
    k_gauss<<<B_, 512>>>(h, gaussw, gaussb, out);
    k_comp<<<dim3(B_, (V_ + 255) / 256), 256>>>(h, compw, compb, out);
}

// round 11
// speedup vs baseline: 6.2695x; 6.2695x over previous
#include <cuda_runtime.h>
#include <cuda_fp16.h>
#include <math.h>

#define B_ 32
#define L_ 64
#define H_ 1024
#define E_ 8
#define V_ 12000
#define OUT_ 16
#define HID_ 512
#define COMP_OFF 512                 // gauss_param occupies out[0:512]
#define LOSS_OFF (512 + 32*64*12000) // scalar at the end
#define NVT 94                       // ceil(12000/128)

// -------------------- scratch (static device globals only) -----------------
__device__ float  g_hid[B_ * HID_];
__device__ int2   g_sel[B_];
__device__ float2 g_gate[B_];
__device__ __half g_h16[B_ * 2 * L_ * H_];   // [b][ei][l][k], gate pre-folded

// ===================== PTX helpers (all plain sm_80+ PTX) ==================
__device__ __forceinline__ unsigned smem_u32(const void* p) {
    unsigned a;
    asm("{ .reg .u64 t; cvta.to.shared.u64 t, %1; cvt.u32.u64 %0, t; }"
        : "=r"(a) : "l"(p));
    return a;
}
__device__ __forceinline__ void cp16(unsigned d, const void* s) {
    asm volatile("cp.async.cg.shared.global [%0], [%1], 16;"
                 :: "r"(d), "l"(s) : "memory");
}
__device__ __forceinline__ void sts128(unsigned a, unsigned x, unsigned y,
                                       unsigned z, unsigned w) {
    asm volatile("st.shared.v4.b32 [%0], {%1,%2,%3,%4};"
                 :: "r"(a), "r"(x), "r"(y), "r"(z), "r"(w) : "memory");
}
__device__ __forceinline__ void ldm_x4(unsigned& r0, unsigned& r1,
                                       unsigned& r2, unsigned& r3, unsigned a) {
    asm volatile("ldmatrix.sync.aligned.m8n8.x4.shared.b16 {%0,%1,%2,%3}, [%4];"
                 : "=r"(r0), "=r"(r1), "=r"(r2), "=r"(r3) : "r"(a));
}
__device__ __forceinline__ void mma16816(float& c0, float& c1, float& c2, float& c3,
                                         unsigned a0, unsigned a1, unsigned a2,
                                         unsigned a3, unsigned b0, unsigned b1) {
    asm volatile(
        "mma.sync.aligned.m16n8k16.row.col.f32.f16.f16.f32 "
        "{%0,%1,%2,%3}, {%4,%5,%6,%7}, {%8,%9}, {%0,%1,%2,%3};"
        : "+f"(c0), "+f"(c1), "+f"(c2), "+f"(c3)
        : "r"(a0), "r"(a1), "r"(a2), "r"(a3), "r"(b0), "r"(b1));
}
__device__ __forceinline__ unsigned h2u(__half2 h) {
    return *reinterpret_cast<unsigned*>(&h);
}
#define SWZ(o) ((o) ^ (((o) >> 3) & 0x70))

// SMEM layout (bytes): A = W f16 [128v x 64k] x2, B = h f16 [64l x 64k] x2
#define SM_A0   0
#define SM_A1   16384
#define SM_B0   32768
#define SM_B1   (32768 + 8192)
#define SMEM_TOTAL 49152

// -------------------- K1: hid = relu(q @ w1 + b1) --------------------------
__global__ void k_hid(const float* __restrict__ q,
                      const float* __restrict__ w1,
                      const float* __restrict__ b1) {
    __shared__ float qs[H_];
    int b = blockIdx.x;
    int j = blockIdx.y * 128 + threadIdx.x;
    for (int i = threadIdx.x; i < H_; i += 128) qs[i] = q[b * H_ + i];
    __syncthreads();
    float acc = b1[j];
#pragma unroll 8
    for (int i = 0; i < H_; ++i) acc = fmaf(qs[i], w1[i * HID_ + j], acc);
    g_hid[b * HID_ + j] = fmaxf(acc, 0.0f);
}

// -------- K2: logits, top-2 softmax gates, importance, moe_loss ------------
__global__ void k_gate(const float* __restrict__ w2,
                       const float* __restrict__ b2,
                       float* __restrict__ out) {
    __shared__ float w2s[HID_ * E_];
    __shared__ float lg[B_ * E_];
    __shared__ float gd[B_ * E_];
    __shared__ float imp[E_];
    int t = threadIdx.x;
    for (int i = t; i < HID_ * E_; i += 256) w2s[i] = w2[i];
    gd[t] = 0.0f;
    __syncthreads();
    {
        int b = t >> 3, e = t & 7;
        float acc = b2[e];
        const float* hb = &g_hid[b * HID_];
#pragma unroll 8
        for (int i = 0; i < HID_; ++i) acc = fmaf(hb[i], w2s[i * E_ + e], acc);
        lg[t] = acc;
    }
    __syncthreads();
    if (t < B_) {
        float v1 = -1e30f, v2 = -1e30f;
        int i1 = 0, i2 = 0;
        for (int e = 0; e < E_; ++e) {
            float v = lg[t * E_ + e];
            if (v > v1)      { v2 = v1; i2 = i1; v1 = v; i1 = e; }
            else if (v > v2) { v2 = v;  i2 = e; }
        }
        float ex = expf(v2 - v1);
        float s = 1.0f + ex;
        float g1 = 1.0f / s, g2 = ex / s;
        g_sel[t] = make_int2(i1, i2);
        g_gate[t] = make_float2(g1, g2);
        gd[t * E_ + i1] = g1;
        gd[t * E_ + i2] = g2;
    }
    __syncthreads();
    if (t < E_) {
        float s = 0.0f;
        for (int b = 0; b < B_; ++b) s += gd[b * E_ + t];
        imp[t] = s;
    }
    __syncthreads();
    if (t == 0) {
        float mean = 0.0f;
        for (int e = 0; e < E_; ++e) mean += imp[e];
        mean *= (1.0f / E_);
        float var = 0.0f;
        for (int e = 0; e < E_; ++e) { float d = imp[e] - mean; var += d * d; }
        var *= (1.0f / (E_ - 1));
        out[LOSS_OFF] = sqrtf(var) / (mean + 1e-10f) * 0.1f;
    }
}

// -------- K2.5: prescale h by gate, round to f16 ---------------------------
__global__ void k_prep(const float* __restrict__ h) {
    int b = blockIdx.x, ei = blockIdx.y;
    float g = ei ? g_gate[b].y : g_gate[b].x;
    const float4* src = (const float4*)(h + (size_t)b * L_ * H_);
    __half2* dst = (__half2*)(g_h16 + ((size_t)(b * 2 + ei)) * L_ * H_);
    for (int i = threadIdx.x; i < L_ * H_ / 4; i += 256) {
        float4 v = src[i];
        dst[2 * i + 0] = __floats2half2_rn(g * v.x, g * v.y);
        dst[2 * i + 1] = __floats2half2_rn(g * v.z, g * v.w);
    }
}

// -------- K3: gauss_param = sigmoid(h_last . mixed_w + mixed_b) ------------
__global__ void k_gauss(const float* __restrict__ h,
                        const float* __restrict__ gw,
                        const float* __restrict__ gb,
                        float* __restrict__ out) {
    int b = blockIdx.x;
    int o = threadIdx.x >> 5;
    int l = threadIdx.x & 31;
    int2 sel = g_sel[b];
    float2 gg = g_gate[b];
    const float* hl  = h + ((size_t)b * L_ + (L_ - 1)) * H_;
    const float* w1p = gw + ((size_t)sel.x * OUT_ + o) * H_;
    const float* w2p = gw + ((size_t)sel.y * OUT_ + o) * H_;
    float a1 = 0.0f, a2 = 0.0f;
    for (int i = l; i < H_; i += 32) {
        float hv = hl[i];
        a1 = fmaf(hv, w1p[i], a1);
        a2 = fmaf(hv, w2p[i], a2);
    }
#pragma unroll
    for (int off = 16; off > 0; off >>= 1) {
        a1 += __shfl_down_sync(0xffffffff, a1, off);
        a2 += __shfl_down_sync(0xffffffff, a2, off);
    }
    if (l == 0) {
        float val = gg.x * a1 + gg.y * a2 +
                    gg.x * gb[sel.x * OUT_ + o] + gg.y * gb[sel.y * OUT_ + o];
        out[b * OUT_ + o] = 1.0f / (1.0f + expf(-val));
    }
}

// -------- K4: comp via ldmatrix + mma.sync (HMMA) --------------------------
// CTA(b, vtile): D[128v x 64l] = sum_{ei,k} W_e[v,k] * (g*h[l,k])
// 8 warps as 4(m) x 2(n), warp tile 32x32, K-slab 64, double-buffered SW128
// smem, cp.async for h (g_h16), LDG->cvt f16->STS for W, fp32 reg accum.
__global__ __launch_bounds__(256)
void k_comp_mma(const float* __restrict__ comp_w,
                const float* __restrict__ comp_b,
                float* __restrict__ out) {
    extern __shared__ __align__(1024) char smem[];
    const unsigned sb = smem_u32(smem);
    const int t = threadIdx.x, wid = t >> 5, lane = t & 31;
    const int warp_m = wid >> 1, warp_n = wid & 1;
    const int b = blockIdx.x;
    const int vbase = blockIdx.y * 128;
    const int2 sel = g_sel[b];
    const float2 gg = g_gate[b];

    const __half* hb16 = g_h16 + (size_t)b * 2 * L_ * H_;

    float c[2][4][4];   // [m16 tile][n8 tile][reg]
#pragma unroll
    for (int i = 0; i < 2; ++i)
#pragma unroll
        for (int j = 0; j < 4; ++j)
#pragma unroll
            for (int k = 0; k < 4; ++k) c[i][j][k] = 0.0f;

    // ---- prologue: cp.async B(0), LDG W(0) into regs ----
#pragma unroll
    for (int j = 0; j < 2; ++j) {
        int tau = t + 256 * j, r = tau >> 3, cc = tau & 7;
        cp16(sb + SM_B0 + SWZ(r * 128 + cc * 16), hb16 + r * H_ + cc * 8);
    }
    asm volatile("cp.async.commit_group;" ::: "memory");

    float4 wreg[8];
    {
        const float* Wb = comp_w + (size_t)sel.x * V_ * H_;
#pragma unroll
        for (int j = 0; j < 4; ++j) {
            int tau = t + 256 * j, r = tau >> 3, cc = tau & 7;
            int v = vbase + r; if (v >= V_) v = V_ - 1;
            const float4* p = (const float4*)(Wb + (size_t)v * H_ + cc * 8);
            wreg[2 * j] = p[0]; wreg[2 * j + 1] = p[1];
        }
    }

    // per-lane ldmatrix byte offsets (within a tile)
    //   A: row = m0 + (l&7) + ((l>>3)&1)*8, kbyte += ((l>>4)&1)*16
    const int a_row = warp_m * 32 + (lane & 7) + ((lane >> 3) & 1) * 8;
    const int a_kb  = ((lane >> 4) & 1) * 16;
    //   B: row = n0 + (l&7) + ((l>>4)&1)*8, kbyte += ((l>>3)&1)*16
    const int b_row = warp_n * 32 + (lane & 7) + ((lane >> 4) & 1) * 8;
    const int b_kb  = ((lane >> 3) & 1) * 16;

    for (int s = 0; s < 32; ++s) {
        const unsigned Ab = sb + ((s & 1) ? SM_A1 : SM_A0);
        const unsigned Bb = sb + ((s & 1) ? SM_B1 : SM_B0);
        const unsigned Bn = sb + ((s & 1) ? SM_B0 : SM_B1);

        // B(s) landed (only outstanding group)
        asm volatile("cp.async.wait_group 0;" ::: "memory");

        // store W(s) as f16 into Ab (safe: last reader was compute(s-2))
#pragma unroll
        for (int j = 0; j < 4; ++j) {
            int tau = t + 256 * j, r = tau >> 3, cc = tau & 7;
            __half2 h0 = __floats2half2_rn(wreg[2 * j].x,     wreg[2 * j].y);
            __half2 h1 = __floats2half2_rn(wreg[2 * j].z,     wreg[2 * j].w);
            __half2 h2 = __floats2half2_rn(wreg[2 * j + 1].x, wreg[2 * j + 1].y);
            __half2 h3 = __floats2half2_rn(wreg[2 * j + 1].z, wreg[2 * j + 1].w);
            sts128(Ab + SWZ(r * 128 + cc * 16), h2u(h0), h2u(h1), h2u(h2), h2u(h3));
        }

        // prefetch W(s+1) into regs (hidden behind sync + compute)
        if (s + 1 < 32) {
            int sn = s + 1, ei = sn >> 4, k0 = (sn & 15) * 64;
            int e = ei ? sel.y : sel.x;
            const float* Wb = comp_w + (size_t)e * V_ * H_ + k0;
#pragma unroll
            for (int j = 0; j < 4; ++j) {
                int tau = t + 256 * j, r = tau >> 3, cc = tau & 7;
                int v = vbase + r; if (v >= V_) v = V_ - 1;
                const float4* p = (const float4*)(Wb + (size_t)v * H_ + cc * 8);
                wreg[2 * j] = p[0]; wreg[2 * j + 1] = p[1];
            }
        }

        __syncthreads();   // A(s)/B(s) visible; compute(s-1) done everywhere

        // cp.async B(s+1) — only after sync (compute(s-1) read that buffer)
        if (s + 1 < 32) {
            int sn = s + 1, ei = sn >> 4, k0 = (sn & 15) * 64;
            const __half* src = hb16 + (size_t)ei * L_ * H_ + k0;
#pragma unroll
            for (int j = 0; j < 2; ++j) {
                int tau = t + 256 * j, r = tau >> 3, cc = tau & 7;
                cp16(Bn + SWZ(r * 128 + cc * 16), src + r * H_ + cc * 8);
            }
            asm volatile("cp.async.commit_group;" ::: "memory");
        }

        // ---- compute: 4 k-steps of 16, 8 mma each ----
#pragma unroll
        for (int ks = 0; ks < 4; ++ks) {
            unsigned a[2][4], bf[2][4];
#pragma unroll
            for (int mt = 0; mt < 2; ++mt) {
                unsigned off = (a_row + mt * 16) * 128 + ks * 32 + a_kb;
                ldm_x4(a[mt][0], a[mt][1], a[mt][2], a[mt][3], Ab + SWZ(off));
            }
#pragma unroll
            for (int nt2 = 0; nt2 < 2; ++nt2) {
                unsigned off = (b_row + nt2 * 16) * 128 + ks * 32 + b_kb;
                ldm_x4(bf[nt2][0], bf[nt2][1], bf[nt2][2], bf[nt2][3], Bb + SWZ(off));
            }
#pragma unroll
            for (int mt = 0; mt < 2; ++mt)
#pragma unroll
                for (int nt = 0; nt < 4; ++nt) {
                    unsigned b0 = bf[nt >> 1][(nt & 1) * 2];
                    unsigned b1 = bf[nt >> 1][(nt & 1) * 2 + 1];
                    mma16816(c[mt][nt][0], c[mt][nt][1], c[mt][nt][2], c[mt][nt][3],
                             a[mt][0], a[mt][1], a[mt][2], a[mt][3], b0, b1);
                }
        }
    }

    // ---- epilogue: bias + store (32B-sector coalesced scalar stores) ----
    float* ob = out + COMP_OFF + (size_t)b * L_ * V_;
    const int lq = lane >> 2, ln = (lane & 3) * 2;
#pragma unroll
    for (int mt = 0; mt < 2; ++mt) {
        int v0 = vbase + warp_m * 32 + mt * 16 + lq;
        int v1 = v0 + 8;
        float bias0 = 0.0f, bias1 = 0.0f;
        if (v0 < V_)
            bias0 = gg.x * comp_b[(size_t)sel.x * V_ + v0] +
                    gg.y * comp_b[(size_t)sel.y * V_ + v0];
        if (v1 < V_)
            bias1 = gg.x * comp_b[(size_t)sel.x * V_ + v1] +
                    gg.y * comp_b[(size_t)sel.y * V_ + v1];
#pragma unroll
        for (int nt = 0; nt < 4; ++nt) {
            int l0 = warp_n * 32 + nt * 8 + ln;
            if (v0 < V_) {
                ob[(size_t)l0 * V_ + v0]       = c[mt][nt][0] + bias0;
                ob[(size_t)(l0 + 1) * V_ + v0] = c[mt][nt][1] + bias0;
            }
            if (v1 < V_) {
                ob[(size_t)l0 * V_ + v1]       = c[mt][nt][2] + bias1;
                ob[(size_t)(l0 + 1) * V_ + v1] = c[mt][nt][3] + bias1;
            }
        }
    }
}

// ---------------------------------------------------------------------------
extern "C" void kernel_launch(void* const* d_in, const int* in_sizes, int n_in,
                              void* d_out, int out_size) {
    const float* q      = (const float*)d_in[0];
    const float* h      = (const float*)d_in[1];
    const float* gw1    = (const float*)d_in[2];
    const float* gb1    = (const float*)d_in[3];
    const float* gw2    = (const float*)d_in[4];
    const float* gb2    = (const float*)d_in[5];
    const float* gaussw = (const float*)d_in[6];
    const float* gaussb = (const float*)d_in[7];
    const float* compw  = (const float*)d_in[8];
    const float* compb  = (const float*)d_in[9];
    float* out = (float*)d_out;

    cudaFuncSetAttribute(k_comp_mma, cudaFuncAttributeMaxDynamicSharedMemorySize,
                         SMEM_TOTAL);

    k_hid<<<dim3(B_, 4), 128>>>(q, gw1, gb1);
    k_gate<<<1, 256>>>(gw2, gb2, out);
    k_prep<<<dim3(B_, 2), 256>>>(h);
    k_gauss<<<B_, 512>>>(h, gaussw, gaussb, out);
    k_comp_mma<<<dim3(B_, NVT), 256, SMEM_TOTAL>>>(compw, compb, out);
}

// round 13
// speedup vs baseline: 6.2884x; 1.0030x over previous
#include <cuda_runtime.h>
#include <cuda_fp16.h>
#include <math.h>

#define B_ 32
#define L_ 64
#define H_ 1024
#define E_ 8
#define V_ 12000
#define OUT_ 16
#define HID_ 512
#define COMP_OFF 512                 // gauss_param occupies out[0:512]
#define LOSS_OFF (512 + 32*64*12000) // scalar at the end
#define NVT 94                       // ceil(12000/128)

// -------------------- scratch (static device globals only) -----------------
__device__ float  g_hid[B_ * HID_];
__device__ int2   g_sel[B_];
__device__ float2 g_gate[B_];
__device__ __half g_h16[B_ * 2 * L_ * H_];   // [b][ei][l][k], gate pre-folded

// ===================== PTX helpers (all plain sm_80+ PTX) ==================
__device__ __forceinline__ unsigned smem_u32(const void* p) {
    unsigned a;
    asm("{ .reg .u64 t; cvta.to.shared.u64 t, %1; cvt.u32.u64 %0, t; }"
        : "=r"(a) : "l"(p));
    return a;
}
__device__ __forceinline__ void cp16(unsigned d, const void* s) {
    asm volatile("cp.async.cg.shared.global [%0], [%1], 16;"
                 :: "r"(d), "l"(s) : "memory");
}
__device__ __forceinline__ void sts128(unsigned a, unsigned x, unsigned y,
                                       unsigned z, unsigned w) {
    asm volatile("st.shared.v4.b32 [%0], {%1,%2,%3,%4};"
                 :: "r"(a), "r"(x), "r"(y), "r"(z), "r"(w) : "memory");
}
__device__ __forceinline__ void ldm_x4(unsigned& r0, unsigned& r1,
                                       unsigned& r2, unsigned& r3, unsigned a) {
    asm volatile("ldmatrix.sync.aligned.m8n8.x4.shared.b16 {%0,%1,%2,%3}, [%4];"
                 : "=r"(r0), "=r"(r1), "=r"(r2), "=r"(r3) : "r"(a));
}
__device__ __forceinline__ void mma16816(float& c0, float& c1, float& c2, float& c3,
                                         unsigned a0, unsigned a1, unsigned a2,
                                         unsigned a3, unsigned b0, unsigned b1) {
    asm volatile(
        "mma.sync.aligned.m16n8k16.row.col.f32.f16.f16.f32 "
        "{%0,%1,%2,%3}, {%4,%5,%6,%7}, {%8,%9}, {%0,%1,%2,%3};"
        : "+f"(c0), "+f"(c1), "+f"(c2), "+f"(c3)
        : "r"(a0), "r"(a1), "r"(a2), "r"(a3), "r"(b0), "r"(b1));
}
__device__ __forceinline__ unsigned h2u(__half2 h) {
    return *reinterpret_cast<unsigned*>(&h);
}
#define SWZ(o) ((o) ^ (((o) >> 3) & 0x70))

// SMEM layout (bytes): A = W f16 [128v x 64k] x2, B = h f16 [64l x 64k] x2
#define SM_A0   0
#define SM_A1   16384
#define SM_B0   32768
#define SM_B1   (32768 + 8192)
#define SMEM_TOTAL 49152

// -------------------- K1: hid = relu(q @ w1 + b1) --------------------------
__global__ void k_hid(const float* __restrict__ q,
                      const float* __restrict__ w1,
                      const float* __restrict__ b1) {
    __shared__ float qs[H_];
    int b = blockIdx.x;
    int j = blockIdx.y * 128 + threadIdx.x;
    for (int i = threadIdx.x; i < H_; i += 128) qs[i] = q[b * H_ + i];
    __syncthreads();
    float acc = b1[j];
#pragma unroll 8
    for (int i = 0; i < H_; ++i) acc = fmaf(qs[i], w1[i * HID_ + j], acc);
    g_hid[b * HID_ + j] = fmaxf(acc, 0.0f);
}

// -------- K2: logits, top-2 softmax gates, importance, moe_loss ------------
__global__ void k_gate(const float* __restrict__ w2,
                       const float* __restrict__ b2,
                       float* __restrict__ out) {
    __shared__ float w2s[HID_ * E_];
    __shared__ float lg[B_ * E_];
    __shared__ float gd[B_ * E_];
    __shared__ float imp[E_];
    int t = threadIdx.x;
    for (int i = t; i < HID_ * E_; i += 256) w2s[i] = w2[i];
    gd[t] = 0.0f;
    __syncthreads();
    {
        int b = t >> 3, e = t & 7;
        float acc = b2[e];
        const float* hb = &g_hid[b * HID_];
#pragma unroll 8
        for (int i = 0; i < HID_; ++i) acc = fmaf(hb[i], w2s[i * E_ + e], acc);
        lg[t] = acc;
    }
    __syncthreads();
    if (t < B_) {
        float v1 = -1e30f, v2 = -1e30f;
        int i1 = 0, i2 = 0;
        for (int e = 0; e < E_; ++e) {
            float v = lg[t * E_ + e];
            if (v > v1)      { v2 = v1; i2 = i1; v1 = v; i1 = e; }
            else if (v > v2) { v2 = v;  i2 = e; }
        }
        float ex = expf(v2 - v1);
        float s = 1.0f + ex;
        float g1 = 1.0f / s, g2 = ex / s;
        g_sel[t] = make_int2(i1, i2);
        g_gate[t] = make_float2(g1, g2);
        gd[t * E_ + i1] = g1;
        gd[t * E_ + i2] = g2;
    }
    __syncthreads();
    if (t < E_) {
        float s = 0.0f;
        for (int b = 0; b < B_; ++b) s += gd[b * E_ + t];
        imp[t] = s;
    }
    __syncthreads();
    if (t == 0) {
        float mean = 0.0f;
        for (int e = 0; e < E_; ++e) mean += imp[e];
        mean *= (1.0f / E_);
        float var = 0.0f;
        for (int e = 0; e < E_; ++e) { float d = imp[e] - mean; var += d * d; }
        var *= (1.0f / (E_ - 1));
        out[LOSS_OFF] = sqrtf(var) / (mean + 1e-10f) * 0.1f;
    }
}

// -------- K2.5: prescale h by gate, round to f16 ---------------------------
__global__ void k_prep(const float* __restrict__ h) {
    int b = blockIdx.x, ei = blockIdx.y;
    float g = ei ? g_gate[b].y : g_gate[b].x;
    const float4* src = (const float4*)(h + (size_t)b * L_ * H_);
    __half2* dst = (__half2*)(g_h16 + ((size_t)(b * 2 + ei)) * L_ * H_);
    for (int i = threadIdx.x; i < L_ * H_ / 4; i += 256) {
        float4 v = src[i];
        dst[2 * i + 0] = __floats2half2_rn(g * v.x, g * v.y);
        dst[2 * i + 1] = __floats2half2_rn(g * v.z, g * v.w);
    }
}

// -------- K3: gauss_param = sigmoid(h_last . mixed_w + mixed_b) ------------
// grid (B, OUT), 64 threads: warp 0 -> expert sel.x, warp 1 -> expert sel.y.
__global__ void k_gauss(const float* __restrict__ h,
                        const float* __restrict__ gw,
                        const float* __restrict__ gb,
                        float* __restrict__ out) {
    __shared__ float part[2];
    int b = blockIdx.x, o = blockIdx.y;
    int w = threadIdx.x >> 5, l = threadIdx.x & 31;
    int2 sel = g_sel[b];
    float2 gg = g_gate[b];
    int e = w ? sel.y : sel.x;
    float g = w ? gg.y : gg.x;
    const float* hl = h + ((size_t)b * L_ + (L_ - 1)) * H_;
    const float* wp = gw + ((size_t)e * OUT_ + o) * H_;
    float a = 0.0f;
#pragma unroll 8
    for (int i = l; i < H_; i += 32) a = fmaf(hl[i], wp[i], a);
#pragma unroll
    for (int off = 16; off > 0; off >>= 1)
        a += __shfl_down_sync(0xffffffff, a, off);
    if (l == 0) part[w] = g * (a + gb[e * OUT_ + o]);
    __syncthreads();
    if (threadIdx.x == 0) {
        float val = part[0] + part[1];
        out[b * OUT_ + o] = 1.0f / (1.0f + expf(-val));
    }
}

// -------- K4: comp via ldmatrix + mma.sync (HMMA) --------------------------
// CTA(b, vtile): D[128v x 64l] = sum_{ei,k} W_e[v,k] * (g*h[l,k])
// 8 warps as 4(m) x 2(n), warp tile 32x32, K-slab 64, double-buffered SW128
// smem, cp.async for h (g_h16), LDG->cvt f16->STS for W, fp32 reg accum.
// 2 CTAs/SM (96KB smem, <=128 regs) to hide barrier + L2 latency.
__global__ __launch_bounds__(256, 2)
void k_comp_mma(const float* __restrict__ comp_w,
                const float* __restrict__ comp_b,
                float* __restrict__ out) {
    extern __shared__ __align__(1024) char smem[];
    const unsigned sb = smem_u32(smem);
    const int t = threadIdx.x, wid = t >> 5, lane = t & 31;
    const int warp_m = wid >> 1, warp_n = wid & 1;
    const int b = blockIdx.x;
    const int vbase = blockIdx.y * 128;
    const int2 sel = g_sel[b];
    const float2 gg = g_gate[b];

    const __half* hb16 = g_h16 + (size_t)b * 2 * L_ * H_;

    float c[2][4][4];   // [m16 tile][n8 tile][reg]
#pragma unroll
    for (int i = 0; i < 2; ++i)
#pragma unroll
        for (int j = 0; j < 4; ++j)
#pragma unroll
            for (int k = 0; k < 4; ++k) c[i][j][k] = 0.0f;

    // ---- prologue: cp.async B(0), LDG W(0) into regs ----
#pragma unroll
    for (int j = 0; j < 2; ++j) {
        int tau = t + 256 * j, r = tau >> 3, cc = tau & 7;
        cp16(sb + SM_B0 + SWZ(r * 128 + cc * 16), hb16 + r * H_ + cc * 8);
    }
    asm volatile("cp.async.commit_group;" ::: "memory");

    float4 wreg[8];
    {
        const float* Wb = comp_w + (size_t)sel.x * V_ * H_;
#pragma unroll
        for (int j = 0; j < 4; ++j) {
            int tau = t + 256 * j, r = tau >> 3, cc = tau & 7;
            int v = vbase + r; if (v >= V_) v = V_ - 1;
            const float4* p = (const float4*)(Wb + (size_t)v * H_ + cc * 8);
            wreg[2 * j] = p[0]; wreg[2 * j + 1] = p[1];
        }
    }

    // per-lane ldmatrix byte offsets (within a tile)
    const int a_row = warp_m * 32 + (lane & 7) + ((lane >> 3) & 1) * 8;
    const int a_kb  = ((lane >> 4) & 1) * 16;
    const int b_row = warp_n * 32 + (lane & 7) + ((lane >> 4) & 1) * 8;
    const int b_kb  = ((lane >> 3) & 1) * 16;

    for (int s = 0; s < 32; ++s) {
        const unsigned Ab = sb + ((s & 1) ? SM_A1 : SM_A0);
        const unsigned Bb = sb + ((s & 1) ? SM_B1 : SM_B0);
        const unsigned Bn = sb + ((s & 1) ? SM_B0 : SM_B1);

        // B(s) landed (only outstanding group)
        asm volatile("cp.async.wait_group 0;" ::: "memory");

        // store W(s) as f16 into Ab (safe: last reader was compute(s-2))
#pragma unroll
        for (int j = 0; j < 4; ++j) {
            int tau = t + 256 * j, r = tau >> 3, cc = tau & 7;
            __half2 h0 = __floats2half2_rn(wreg[2 * j].x,     wreg[2 * j].y);
            __half2 h1 = __floats2half2_rn(wreg[2 * j].z,     wreg[2 * j].w);
            __half2 h2 = __floats2half2_rn(wreg[2 * j + 1].x, wreg[2 * j + 1].y);
            __half2 h3 = __floats2half2_rn(wreg[2 * j + 1].z, wreg[2 * j + 1].w);
            sts128(Ab + SWZ(r * 128 + cc * 16), h2u(h0), h2u(h1), h2u(h2), h2u(h3));
        }

        // prefetch W(s+1) into regs (hidden behind sync + compute)
        if (s + 1 < 32) {
            int sn = s + 1, ei = sn >> 4, k0 = (sn & 15) * 64;
            int e = ei ? sel.y : sel.x;
            const float* Wb = comp_w + (size_t)e * V_ * H_ + k0;
#pragma unroll
            for (int j = 0; j < 4; ++j) {
                int tau = t + 256 * j, r = tau >> 3, cc = tau & 7;
                int v = vbase + r; if (v >= V_) v = V_ - 1;
                const float4* p = (const float4*)(Wb + (size_t)v * H_ + cc * 8);
                wreg[2 * j] = p[0]; wreg[2 * j + 1] = p[1];
            }
        }

        __syncthreads();   // A(s)/B(s) visible; compute(s-1) done everywhere

        // cp.async B(s+1) — only after sync (compute(s-1) read that buffer)
        if (s + 1 < 32) {
            int sn = s + 1, ei = sn >> 4, k0 = (sn & 15) * 64;
            const __half* src = hb16 + (size_t)ei * L_ * H_ + k0;
#pragma unroll
            for (int j = 0; j < 2; ++j) {
                int tau = t + 256 * j, r = tau >> 3, cc = tau & 7;
                cp16(Bn + SWZ(r * 128 + cc * 16), src + r * H_ + cc * 8);
            }
            asm volatile("cp.async.commit_group;" ::: "memory");
        }

        // ---- compute: 4 k-steps of 16, 8 mma each ----
#pragma unroll
        for (int ks = 0; ks < 4; ++ks) {
            unsigned a[2][4], bf[2][4];
#pragma unroll
            for (int mt = 0; mt < 2; ++mt) {
                unsigned off = (a_row + mt * 16) * 128 + ks * 32 + a_kb;
                ldm_x4(a[mt][0], a[mt][1], a[mt][2], a[mt][3], Ab + SWZ(off));
            }
#pragma unroll
            for (int nt2 = 0; nt2 < 2; ++nt2) {
                unsigned off = (b_row + nt2 * 16) * 128 + ks * 32 + b_kb;
                ldm_x4(bf[nt2][0], bf[nt2][1], bf[nt2][2], bf[nt2][3], Bb + SWZ(off));
            }
#pragma unroll
            for (int mt = 0; mt < 2; ++mt)
#pragma unroll
                for (int nt = 0; nt < 4; ++nt) {
                    unsigned b0 = bf[nt >> 1][(nt & 1) * 2];
                    unsigned b1 = bf[nt >> 1][(nt & 1) * 2 + 1];
                    mma16816(c[mt][nt][0], c[mt][nt][1], c[mt][nt][2], c[mt][nt][3],
                             a[mt][0], a[mt][1], a[mt][2], a[mt][3], b0, b1);
                }
        }
    }

    // ---- epilogue: bias + store (32B-sector coalesced scalar stores) ----
    float* ob = out + COMP_OFF + (size_t)b * L_ * V_;
    const int lq = lane >> 2, ln = (lane & 3) * 2;
#pragma unroll
    for (int mt = 0; mt < 2; ++mt) {
        int v0 = vbase + warp_m * 32 + mt * 16 + lq;
        int v1 = v0 + 8;
        float bias0 = 0.0f, bias1 = 0.0f;
        if (v0 < V_)
            bias0 = gg.x * comp_b[(size_t)sel.x * V_ + v0] +
                    gg.y * comp_b[(size_t)sel.y * V_ + v0];
        if (v1 < V_)
            bias1 = gg.x * comp_b[(size_t)sel.x * V_ + v1] +
                    gg.y * comp_b[(size_t)sel.y * V_ + v1];
#pragma unroll
        for (int nt = 0; nt < 4; ++nt) {
            int l0 = warp_n * 32 + nt * 8 + ln;
            if (v0 < V_) {
                ob[(size_t)l0 * V_ + v0]       = c[mt][nt][0] + bias0;
                ob[(size_t)(l0 + 1) * V_ + v0] = c[mt][nt][1] + bias0;
            }
            if (v1 < V_) {
                ob[(size_t)l0 * V_ + v1]       = c[mt][nt][2] + bias1;
                ob[(size_t)(l0 + 1) * V_ + v1] = c[mt][nt][3] + bias1;
            }
        }
    }
}

// ---------------------------------------------------------------------------
extern "C" void kernel_launch(void* const* d_in, const int* in_sizes, int n_in,
                              void* d_out, int out_size) {
    const float* q      = (const float*)d_in[0];
    const float* h      = (const float*)d_in[1];
    const float* gw1    = (const float*)d_in[2];
    const float* gb1    = (const float*)d_in[3];
    const float* gw2    = (const float*)d_in[4];
    const float* gb2    = (const float*)d_in[5];
    const float* gaussw = (const float*)d_in[6];
    const float* gaussb = (const float*)d_in[7];
    const float* compw  = (const float*)d_in[8];
    const float* compb  = (const float*)d_in[9];
    float* out = (float*)d_out;

    cudaFuncSetAttribute(k_comp_mma, cudaFuncAttributeMaxDynamicSharedMemorySize,
                         SMEM_TOTAL);

    k_hid<<<dim3(B_, 4), 128>>>(q, gw1, gb1);
    k_gate<<<1, 256>>>(gw2, gb2, out);
    k_prep<<<dim3(B_, 2), 256>>>(h);
    k_gauss<<<dim3(B_, OUT_), 64>>>(h, gaussw, gaussb, out);
    k_comp_mma<<<dim3(B_, NVT), 256, SMEM_TOTAL>>>(compw, compb, out);
}

// round 14
// speedup vs baseline: 7.1116x; 1.1309x over previous
#include <cuda_runtime.h>
#include <cuda_fp16.h>
#include <math.h>

#define B_ 32
#define L_ 64
#define H_ 1024
#define E_ 8
#define V_ 12000
#define OUT_ 16
#define HID_ 512
#define COMP_OFF 512                 // gauss_param occupies out[0:512]
#define LOSS_OFF (512 + 32*64*12000) // scalar at the end
#define NVT 94                       // ceil(12000/128)
#define NJOBS 22                     // max sum_e ceil(|S_e|/4), sum|S_e|=64

// -------------------- scratch (static device globals only) -----------------
__device__ float  g_hid[B_ * HID_];
__device__ int2   g_sel[B_];
__device__ float2 g_gate[B_];
__device__ __half g_h16[B_ * 2 * L_ * H_];   // [b][ei][l][k], gate pre-folded
// expert-grouped job table (built by k_gate thread 0)
__device__ int    g_job_e[NJOBS];
__device__ int    g_job_nb[NJOBS];
__device__ int    g_job_b[NJOBS * 4];
__device__ int    g_job_h[NJOBS * 4];        // index into g_h16 (b*2+ei)

// ===================== PTX helpers (all plain sm_80+ PTX) ==================
__device__ __forceinline__ unsigned smem_u32(const void* p) {
    unsigned a;
    asm("{ .reg .u64 t; cvta.to.shared.u64 t, %1; cvt.u32.u64 %0, t; }"
        : "=r"(a) : "l"(p));
    return a;
}
__device__ __forceinline__ void cp16(unsigned d, const void* s) {
    asm volatile("cp.async.cg.shared.global [%0], [%1], 16;"
                 :: "r"(d), "l"(s) : "memory");
}
__device__ __forceinline__ void sts128(unsigned a, unsigned x, unsigned y,
                                       unsigned z, unsigned w) {
    asm volatile("st.shared.v4.b32 [%0], {%1,%2,%3,%4};"
                 :: "r"(a), "r"(x), "r"(y), "r"(z), "r"(w) : "memory");
}
__device__ __forceinline__ void ldm_x4(unsigned& r0, unsigned& r1,
                                       unsigned& r2, unsigned& r3, unsigned a) {
    asm volatile("ldmatrix.sync.aligned.m8n8.x4.shared.b16 {%0,%1,%2,%3}, [%4];"
                 : "=r"(r0), "=r"(r1), "=r"(r2), "=r"(r3) : "r"(a));
}
__device__ __forceinline__ void mma16816(float& c0, float& c1, float& c2, float& c3,
                                         unsigned a0, unsigned a1, unsigned a2,
                                         unsigned a3, unsigned b0, unsigned b1) {
    asm volatile(
        "mma.sync.aligned.m16n8k16.row.col.f32.f16.f16.f32 "
        "{%0,%1,%2,%3}, {%4,%5,%6,%7}, {%8,%9}, {%0,%1,%2,%3};"
        : "+f"(c0), "+f"(c1), "+f"(c2), "+f"(c3)
        : "r"(a0), "r"(a1), "r"(a2), "r"(a3), "r"(b0), "r"(b1));
}
__device__ __forceinline__ unsigned h2u(__half2 h) {
    return *reinterpret_cast<unsigned*>(&h);
}
#define SWZ(o) ((o) ^ (((o) >> 3) & 0x70))

// SMEM: A = W f16 [128v x 64k] x2 buffers; B = h f16 [64l x 64k] x2 x 4 b's
#define SM_A0   0
#define SM_A1   16384
#define SM_B(buf, bb) (32768 + (buf) * 32768 + (bb) * 8192)
#define SMEM_TOTAL 98304

// -------------------- K1: hid = relu(q @ w1 + b1) --------------------------
__global__ void k_hid(const float* __restrict__ q,
                      const float* __restrict__ w1,
                      const float* __restrict__ b1) {
    __shared__ float qs[H_];
    int b = blockIdx.x;
    int j = blockIdx.y * 128 + threadIdx.x;
    for (int i = threadIdx.x; i < H_; i += 128) qs[i] = q[b * H_ + i];
    __syncthreads();
    float acc = b1[j];
#pragma unroll 8
    for (int i = 0; i < H_; ++i) acc = fmaf(qs[i], w1[i * HID_ + j], acc);
    g_hid[b * HID_ + j] = fmaxf(acc, 0.0f);
}

// -------- K2: logits, top-2 gates, moe_loss, expert-grouped job table ------
__global__ void k_gate(const float* __restrict__ w2,
                       const float* __restrict__ b2,
                       float* __restrict__ out) {
    __shared__ float w2s[HID_ * E_];
    __shared__ float lg[B_ * E_];
    __shared__ float gd[B_ * E_];
    __shared__ float imp[E_];
    int t = threadIdx.x;
    for (int i = t; i < HID_ * E_; i += 256) w2s[i] = w2[i];
    gd[t] = 0.0f;
    __syncthreads();
    {
        int b = t >> 3, e = t & 7;
        float acc = b2[e];
        const float* hb = &g_hid[b * HID_];
#pragma unroll 8
        for (int i = 0; i < HID_; ++i) acc = fmaf(hb[i], w2s[i * E_ + e], acc);
        lg[t] = acc;
    }
    __syncthreads();
    if (t < B_) {
        float v1 = -1e30f, v2 = -1e30f;
        int i1 = 0, i2 = 0;
        for (int e = 0; e < E_; ++e) {
            float v = lg[t * E_ + e];
            if (v > v1)      { v2 = v1; i2 = i1; v1 = v; i1 = e; }
            else if (v > v2) { v2 = v;  i2 = e; }
        }
        float ex = expf(v2 - v1);
        float s = 1.0f + ex;
        float g1 = 1.0f / s, g2 = ex / s;
        g_sel[t] = make_int2(i1, i2);
        g_gate[t] = make_float2(g1, g2);
        gd[t * E_ + i1] = g1;
        gd[t * E_ + i2] = g2;
    }
    __syncthreads();
    if (t < E_) {
        float s = 0.0f;
        for (int b = 0; b < B_; ++b) s += gd[b * E_ + t];
        imp[t] = s;
    }
    __syncthreads();
    if (t == 0) {
        float mean = 0.0f;
        for (int e = 0; e < E_; ++e) mean += imp[e];
        mean *= (1.0f / E_);
        float var = 0.0f;
        for (int e = 0; e < E_; ++e) { float d = imp[e] - mean; var += d * d; }
        var *= (1.0f / (E_ - 1));
        out[LOSS_OFF] = sqrtf(var) / (mean + 1e-10f) * 0.1f;

        // ---- build expert-grouped jobs (<=4 b's per job, same expert) ----
        int nj = 0;
        for (int e = 0; e < E_; ++e) {
            int cb[4], ch[4], cnt = 0;
            for (int b = 0; b < B_; ++b) {
                int2 sv = g_sel[b];
                int ei = (sv.x == e) ? 0 : ((sv.y == e) ? 1 : -1);
                if (ei < 0) continue;
                cb[cnt] = b; ch[cnt] = b * 2 + ei; ++cnt;
                if (cnt == 4) {
                    g_job_e[nj] = e; g_job_nb[nj] = 4;
                    for (int i2 = 0; i2 < 4; ++i2) {
                        g_job_b[nj * 4 + i2] = cb[i2];
                        g_job_h[nj * 4 + i2] = ch[i2];
                    }
                    ++nj; cnt = 0;
                }
            }
            if (cnt > 0) {
                g_job_e[nj] = e; g_job_nb[nj] = cnt;
                for (int i2 = 0; i2 < cnt; ++i2) {
                    g_job_b[nj * 4 + i2] = cb[i2];
                    g_job_h[nj * 4 + i2] = ch[i2];
                }
                ++nj;
            }
        }
        for (; nj < NJOBS; ++nj) g_job_nb[nj] = 0;
    }
}

// -------- K2.5: prescale h by gate, round to f16 ---------------------------
__global__ void k_prep(const float* __restrict__ h) {
    int b = blockIdx.x, ei = blockIdx.y;
    float g = ei ? g_gate[b].y : g_gate[b].x;
    const float4* src = (const float4*)(h + (size_t)b * L_ * H_);
    __half2* dst = (__half2*)(g_h16 + ((size_t)(b * 2 + ei)) * L_ * H_);
    for (int i = threadIdx.x; i < L_ * H_ / 4; i += 256) {
        float4 v = src[i];
        dst[2 * i + 0] = __floats2half2_rn(g * v.x, g * v.y);
        dst[2 * i + 1] = __floats2half2_rn(g * v.z, g * v.w);
    }
}

// -------- K3: gauss_param = sigmoid(h_last . mixed_w + mixed_b) ------------
__global__ void k_gauss(const float* __restrict__ h,
                        const float* __restrict__ gw,
                        const float* __restrict__ gb,
                        float* __restrict__ out) {
    __shared__ float part[2];
    int b = blockIdx.x, o = blockIdx.y;
    int w = threadIdx.x >> 5, l = threadIdx.x & 31;
    int2 sel = g_sel[b];
    float2 gg = g_gate[b];
    int e = w ? sel.y : sel.x;
    float g = w ? gg.y : gg.x;
    const float* hl = h + ((size_t)b * L_ + (L_ - 1)) * H_;
    const float* wp = gw + ((size_t)e * OUT_ + o) * H_;
    float a = 0.0f;
#pragma unroll 8
    for (int i = l; i < H_; i += 32) a = fmaf(hl[i], wp[i], a);
#pragma unroll
    for (int off = 16; off > 0; off >>= 1)
        a += __shfl_down_sync(0xffffffff, a, off);
    if (l == 0) part[w] = g * (a + gb[e * OUT_ + o]);
    __syncthreads();
    if (threadIdx.x == 0) {
        float val = part[0] + part[1];
        out[b * OUT_ + o] = 1.0f / (1.0f + expf(-val));
    }
}

// -------- K3.5: init comp output with gated bias ---------------------------
__global__ void k_init(const float* __restrict__ comp_b,
                       float* __restrict__ out) {
    int b = blockIdx.x, l = blockIdx.y;
    int2 sel = g_sel[b];
    float2 gg = g_gate[b];
    const float4* c1 = (const float4*)(comp_b + (size_t)sel.x * V_);
    const float4* c2 = (const float4*)(comp_b + (size_t)sel.y * V_);
    float4* o = (float4*)(out + COMP_OFF + ((size_t)b * L_ + l) * V_);
    for (int i = threadIdx.x; i < V_ / 4; i += 256) {
        float4 a = c1[i], d = c2[i], r;
        r.x = gg.x * a.x + gg.y * d.x;
        r.y = gg.x * a.y + gg.y * d.y;
        r.z = gg.x * a.z + gg.y * d.z;
        r.w = gg.x * a.w + gg.y * d.w;
        o[i] = r;
    }
}

// -------- K4: comp via expert-grouped HMMA jobs ----------------------------
// CTA(job, vtile): one expert's W tile [128v x 1024k] against NB<=4 b's'
// gate-folded h16 (N=64 each). W loaded once, shared across b's (4x less L2).
// Results accumulated into out via atomicAdd (bias pre-written by k_init).
template <int NB>
__device__ __forceinline__ void comp_body(const float* __restrict__ comp_w,
                                          float* __restrict__ out,
                                          unsigned sb, int job, int vbase) {
    const int t = threadIdx.x, wid = t >> 5, lane = t & 31;
    const int warp_m = wid >> 1, warp_n = wid & 1;
    const int e = g_job_e[job];

    int jh[NB], jb[NB];
#pragma unroll
    for (int bi = 0; bi < NB; ++bi) {
        jh[bi] = g_job_h[job * 4 + bi];
        jb[bi] = g_job_b[job * 4 + bi];
    }

    float c[NB][2][4][4];
#pragma unroll
    for (int bi = 0; bi < NB; ++bi)
#pragma unroll
        for (int i = 0; i < 2; ++i)
#pragma unroll
            for (int j = 0; j < 4; ++j)
#pragma unroll
                for (int k = 0; k < 4; ++k) c[bi][i][j][k] = 0.0f;

    // ---- prologue: cp.async h(0) for all NB, LDG W(0) into regs ----
#pragma unroll
    for (int bi = 0; bi < NB; ++bi) {
        const __half* src = g_h16 + (size_t)jh[bi] * L_ * H_;
#pragma unroll
        for (int j = 0; j < 2; ++j) {
            int idx = t + 256 * j, r = idx >> 3, cc = idx & 7;
            cp16(sb + SM_B(0, bi) + SWZ(r * 128 + cc * 16), src + r * H_ + cc * 8);
        }
    }
    asm volatile("cp.async.commit_group;" ::: "memory");

    const float* We = comp_w + (size_t)e * V_ * H_;
    float4 wreg[8];
#pragma unroll
    for (int j = 0; j < 4; ++j) {
        int tau = t + 256 * j, r = tau >> 3, cc = tau & 7;
        int v = vbase + r; if (v >= V_) v = V_ - 1;
        const float4* p = (const float4*)(We + (size_t)v * H_ + cc * 8);
        wreg[2 * j] = p[0]; wreg[2 * j + 1] = p[1];
    }

    const int a_row = warp_m * 32 + (lane & 7) + ((lane >> 3) & 1) * 8;
    const int a_kb  = ((lane >> 4) & 1) * 16;
    const int b_row = warp_n * 32 + (lane & 7) + ((lane >> 4) & 1) * 8;
    const int b_kb  = ((lane >> 3) & 1) * 16;

    for (int s = 0; s < 16; ++s) {
        const unsigned Ab = sb + ((s & 1) ? SM_A1 : SM_A0);

        asm volatile("cp.async.wait_group 0;" ::: "memory");

        // store W(s) as f16 (other buffer than compute(s-1) reads)
#pragma unroll
        for (int j = 0; j < 4; ++j) {
            int tau = t + 256 * j, r = tau >> 3, cc = tau & 7;
            __half2 h0 = __floats2half2_rn(wreg[2 * j].x,     wreg[2 * j].y);
            __half2 h1 = __floats2half2_rn(wreg[2 * j].z,     wreg[2 * j].w);
            __half2 h2 = __floats2half2_rn(wreg[2 * j + 1].x, wreg[2 * j + 1].y);
            __half2 h3 = __floats2half2_rn(wreg[2 * j + 1].z, wreg[2 * j + 1].w);
            sts128(Ab + SWZ(r * 128 + cc * 16), h2u(h0), h2u(h1), h2u(h2), h2u(h3));
        }

        if (s + 1 < 16) {
            int k0 = (s + 1) * 64;
#pragma unroll
            for (int j = 0; j < 4; ++j) {
                int tau = t + 256 * j, r = tau >> 3, cc = tau & 7;
                int v = vbase + r; if (v >= V_) v = V_ - 1;
                const float4* p = (const float4*)(We + (size_t)v * H_ + k0 + cc * 8);
                wreg[2 * j] = p[0]; wreg[2 * j + 1] = p[1];
            }
        }

        __syncthreads();

        if (s + 1 < 16) {
            int k0 = (s + 1) * 64, buf = (s + 1) & 1;
#pragma unroll
            for (int bi = 0; bi < NB; ++bi) {
                const __half* src = g_h16 + (size_t)jh[bi] * L_ * H_ + k0;
#pragma unroll
                for (int j = 0; j < 2; ++j) {
                    int idx = t + 256 * j, r = idx >> 3, cc = idx & 7;
                    cp16(sb + SM_B(buf, bi) + SWZ(r * 128 + cc * 16),
                         src + r * H_ + cc * 8);
                }
            }
            asm volatile("cp.async.commit_group;" ::: "memory");
        }

        // ---- compute: 4 k-steps; A ldm shared across all NB b's ----
#pragma unroll
        for (int ks = 0; ks < 4; ++ks) {
            unsigned a[2][4];
#pragma unroll
            for (int mt = 0; mt < 2; ++mt) {
                unsigned off = (a_row + mt * 16) * 128 + ks * 32 + a_kb;
                ldm_x4(a[mt][0], a[mt][1], a[mt][2], a[mt][3], Ab + SWZ(off));
            }
#pragma unroll
            for (int bi = 0; bi < NB; ++bi) {
                const unsigned Bb = sb + SM_B(s & 1, bi);
                unsigned bf[2][4];
#pragma unroll
                for (int nt2 = 0; nt2 < 2; ++nt2) {
                    unsigned off = (b_row + nt2 * 16) * 128 + ks * 32 + b_kb;
                    ldm_x4(bf[nt2][0], bf[nt2][1], bf[nt2][2], bf[nt2][3],
                           Bb + SWZ(off));
                }
#pragma unroll
                for (int mt = 0; mt < 2; ++mt)
#pragma unroll
                    for (int nt = 0; nt < 4; ++nt) {
                        unsigned b0 = bf[nt >> 1][(nt & 1) * 2];
                        unsigned b1 = bf[nt >> 1][(nt & 1) * 2 + 1];
                        mma16816(c[bi][mt][nt][0], c[bi][mt][nt][1],
                                 c[bi][mt][nt][2], c[bi][mt][nt][3],
                                 a[mt][0], a[mt][1], a[mt][2], a[mt][3], b0, b1);
                    }
            }
        }
    }

    // ---- epilogue: atomicAdd into bias-initialized out ----
    const int lq = lane >> 2, ln = (lane & 3) * 2;
#pragma unroll
    for (int bi = 0; bi < NB; ++bi) {
        float* ob = out + COMP_OFF + (size_t)jb[bi] * L_ * V_;
#pragma unroll
        for (int mt = 0; mt < 2; ++mt) {
            int v0 = vbase + warp_m * 32 + mt * 16 + lq;
            int v1 = v0 + 8;
#pragma unroll
            for (int nt = 0; nt < 4; ++nt) {
                int l0 = warp_n * 32 + nt * 8 + ln;
                if (v0 < V_) {
                    atomicAdd(&ob[(size_t)l0 * V_ + v0],       c[bi][mt][nt][0]);
                    atomicAdd(&ob[(size_t)(l0 + 1) * V_ + v0], c[bi][mt][nt][1]);
                }
                if (v1 < V_) {
                    atomicAdd(&ob[(size_t)l0 * V_ + v1],       c[bi][mt][nt][2]);
                    atomicAdd(&ob[(size_t)(l0 + 1) * V_ + v1], c[bi][mt][nt][3]);
                }
            }
        }
    }
}

__global__ __launch_bounds__(256)
void k_comp_mma(const float* __restrict__ comp_w,
                float* __restrict__ out) {
    const int job = blockIdx.x;
    const int nb = g_job_nb[job];
    if (nb == 0) return;
    extern __shared__ __align__(1024) char smem[];
    const unsigned sb = smem_u32(smem);
    const int vbase = blockIdx.y * 128;
    switch (nb) {
        case 4:  comp_body<4>(comp_w, out, sb, job, vbase); break;
        case 3:  comp_body<3>(comp_w, out, sb, job, vbase); break;
        case 2:  comp_body<2>(comp_w, out, sb, job, vbase); break;
        default: comp_body<1>(comp_w, out, sb, job, vbase); break;
    }
}

// ---------------------------------------------------------------------------
extern "C" void kernel_launch(void* const* d_in, const int* in_sizes, int n_in,
                              void* d_out, int out_size) {
    const float* q      = (const float*)d_in[0];
    const float* h      = (const float*)d_in[1];
    const float* gw1    = (const float*)d_in[2];
    const float* gb1    = (const float*)d_in[3];
    const float* gw2    = (const float*)d_in[4];
    const float* gb2    = (const float*)d_in[5];
    const float* gaussw = (const float*)d_in[6];
    const float* gaussb = (const float*)d_in[7];
    const float* compw  = (const float*)d_in[8];
    const float* compb  = (const float*)d_in[9];
    float* out = (float*)d_out;

    cudaFuncSetAttribute(k_comp_mma, cudaFuncAttributeMaxDynamicSharedMemorySize,
                         SMEM_TOTAL);

    k_hid<<<dim3(B_, 4), 128>>>(q, gw1, gb1);
    k_gate<<<1, 256>>>(gw2, gb2, out);
    k_prep<<<dim3(B_, 2), 256>>>(h);
    k_gauss<<<dim3(B_, OUT_), 64>>>(h, gaussw, gaussb, out);
    k_init<<<dim3(B_, L_), 256>>>(compb, out);
    k_comp_mma<<<dim3(NJOBS, NVT), 256, SMEM_TOTAL>>>(compw, out);
}

// round 15
// speedup vs baseline: 7.3009x; 1.0266x over previous
#include <cuda_runtime.h>
#include <cuda_fp16.h>
#include <math.h>

#define B_ 32
#define L_ 64
#define H_ 1024
#define E_ 8
#define V_ 12000
#define OUT_ 16
#define HID_ 512
#define COMP_OFF 512                 // gauss_param occupies out[0:512]
#define LOSS_OFF (512 + 32*64*12000) // scalar at the end
#define NVT 94                       // ceil(12000/128)
#define NJOBS 22                     // max sum_e ceil(|S_e|/4), sum|S_e|=64

// -------------------- scratch (static device globals only) -----------------
__device__ float  g_hid[B_ * HID_];
__device__ int2   g_sel[B_];
__device__ float2 g_gate[B_];
__device__ __half g_h16[B_ * 2 * L_ * H_];   // [b][ei][l][k], gate pre-folded
// expert-grouped job table (built by k_gate thread 0)
__device__ int    g_job_e[NJOBS];
__device__ int    g_job_nb[NJOBS];
__device__ int    g_job_b[NJOBS * 4];
__device__ int    g_job_h[NJOBS * 4];        // index into g_h16 (b*2+ei)

// ===================== PTX helpers (all plain sm_80+ PTX) ==================
__device__ __forceinline__ unsigned smem_u32(const void* p) {
    unsigned a;
    asm("{ .reg .u64 t; cvta.to.shared.u64 t, %1; cvt.u32.u64 %0, t; }"
        : "=r"(a) : "l"(p));
    return a;
}
__device__ __forceinline__ void cp16(unsigned d, const void* s) {
    asm volatile("cp.async.cg.shared.global [%0], [%1], 16;"
                 :: "r"(d), "l"(s) : "memory");
}
__device__ __forceinline__ void sts128(unsigned a, unsigned x, unsigned y,
                                       unsigned z, unsigned w) {
    asm volatile("st.shared.v4.b32 [%0], {%1,%2,%3,%4};"
                 :: "r"(a), "r"(x), "r"(y), "r"(z), "r"(w) : "memory");
}
__device__ __forceinline__ void ldm_x4(unsigned& r0, unsigned& r1,
                                       unsigned& r2, unsigned& r3, unsigned a) {
    asm volatile("ldmatrix.sync.aligned.m8n8.x4.shared.b16 {%0,%1,%2,%3}, [%4];"
                 : "=r"(r0), "=r"(r1), "=r"(r2), "=r"(r3) : "r"(a));
}
__device__ __forceinline__ void mma16816(float& c0, float& c1, float& c2, float& c3,
                                         unsigned a0, unsigned a1, unsigned a2,
                                         unsigned a3, unsigned b0, unsigned b1) {
    asm volatile(
        "mma.sync.aligned.m16n8k16.row.col.f32.f16.f16.f32 "
        "{%0,%1,%2,%3}, {%4,%5,%6,%7}, {%8,%9}, {%0,%1,%2,%3};"
        : "+f"(c0), "+f"(c1), "+f"(c2), "+f"(c3)
        : "r"(a0), "r"(a1), "r"(a2), "r"(a3), "r"(b0), "r"(b1));
}
__device__ __forceinline__ unsigned h2u(__half2 h) {
    return *reinterpret_cast<unsigned*>(&h);
}
#define SWZ(o) ((o) ^ (((o) >> 3) & 0x70))

// SMEM: A = W f16 [128v x 64k] x2 buffers; B = h f16 [64l x 64k] x2 x 4 b's
#define SM_A0   0
#define SM_A1   16384
#define SM_B(buf, bb) (32768 + (buf) * 32768 + (bb) * 8192)
#define SMEM_TOTAL 98304

// -------------------- K1: hid = relu(q @ w1 + b1) --------------------------
__global__ void k_hid(const float* __restrict__ q,
                      const float* __restrict__ w1,
                      const float* __restrict__ b1) {
    __shared__ float qs[H_];
    int b = blockIdx.x;
    int j = blockIdx.y * 128 + threadIdx.x;
    for (int i = threadIdx.x; i < H_; i += 128) qs[i] = q[b * H_ + i];
    __syncthreads();
    float acc = b1[j];
#pragma unroll 8
    for (int i = 0; i < H_; ++i) acc = fmaf(qs[i], w1[i * HID_ + j], acc);
    g_hid[b * HID_ + j] = fmaxf(acc, 0.0f);
}

// -------- K2: logits, top-2 gates, moe_loss, expert-grouped job table ------
__global__ void k_gate(const float* __restrict__ w2,
                       const float* __restrict__ b2,
                       float* __restrict__ out) {
    __shared__ float w2s[HID_ * E_];
    __shared__ float lg[B_ * E_];
    __shared__ float gd[B_ * E_];
    __shared__ float imp[E_];
    int t = threadIdx.x;
    for (int i = t; i < HID_ * E_; i += 256) w2s[i] = w2[i];
    gd[t] = 0.0f;
    __syncthreads();
    {
        int b = t >> 3, e = t & 7;
        float acc = b2[e];
        const float* hb = &g_hid[b * HID_];
#pragma unroll 8
        for (int i = 0; i < HID_; ++i) acc = fmaf(hb[i], w2s[i * E_ + e], acc);
        lg[t] = acc;
    }
    __syncthreads();
    if (t < B_) {
        float v1 = -1e30f, v2 = -1e30f;
        int i1 = 0, i2 = 0;
        for (int e = 0; e < E_; ++e) {
            float v = lg[t * E_ + e];
            if (v > v1)      { v2 = v1; i2 = i1; v1 = v; i1 = e; }
            else if (v > v2) { v2 = v;  i2 = e; }
        }
        float ex = expf(v2 - v1);
        float s = 1.0f + ex;
        float g1 = 1.0f / s, g2 = ex / s;
        g_sel[t] = make_int2(i1, i2);
        g_gate[t] = make_float2(g1, g2);
        gd[t * E_ + i1] = g1;
        gd[t * E_ + i2] = g2;
    }
    __syncthreads();
    if (t < E_) {
        float s = 0.0f;
        for (int b = 0; b < B_; ++b) s += gd[b * E_ + t];
        imp[t] = s;
    }
    __syncthreads();
    if (t == 0) {
        float mean = 0.0f;
        for (int e = 0; e < E_; ++e) mean += imp[e];
        mean *= (1.0f / E_);
        float var = 0.0f;
        for (int e = 0; e < E_; ++e) { float d = imp[e] - mean; var += d * d; }
        var *= (1.0f / (E_ - 1));
        out[LOSS_OFF] = sqrtf(var) / (mean + 1e-10f) * 0.1f;

        // ---- build expert-grouped jobs (<=4 b's per job, same expert) ----
        int nj = 0;
        for (int e = 0; e < E_; ++e) {
            int cb[4], ch[4], cnt = 0;
            for (int b = 0; b < B_; ++b) {
                int2 sv = g_sel[b];
                int ei = (sv.x == e) ? 0 : ((sv.y == e) ? 1 : -1);
                if (ei < 0) continue;
                cb[cnt] = b; ch[cnt] = b * 2 + ei; ++cnt;
                if (cnt == 4) {
                    g_job_e[nj] = e; g_job_nb[nj] = 4;
                    for (int i2 = 0; i2 < 4; ++i2) {
                        g_job_b[nj * 4 + i2] = cb[i2];
                        g_job_h[nj * 4 + i2] = ch[i2];
                    }
                    ++nj; cnt = 0;
                }
            }
            if (cnt > 0) {
                g_job_e[nj] = e; g_job_nb[nj] = cnt;
                for (int i2 = 0; i2 < cnt; ++i2) {
                    g_job_b[nj * 4 + i2] = cb[i2];
                    g_job_h[nj * 4 + i2] = ch[i2];
                }
                ++nj;
            }
        }
        for (; nj < NJOBS; ++nj) g_job_nb[nj] = 0;
    }
}

// -------- K2.5: prescale h by gate, round to f16 ---------------------------
__global__ void k_prep(const float* __restrict__ h) {
    int b = blockIdx.x, ei = blockIdx.y;
    float g = ei ? g_gate[b].y : g_gate[b].x;
    const float4* src = (const float4*)(h + (size_t)b * L_ * H_);
    __half2* dst = (__half2*)(g_h16 + ((size_t)(b * 2 + ei)) * L_ * H_);
    for (int i = threadIdx.x; i < L_ * H_ / 4; i += 256) {
        float4 v = src[i];
        dst[2 * i + 0] = __floats2half2_rn(g * v.x, g * v.y);
        dst[2 * i + 1] = __floats2half2_rn(g * v.z, g * v.w);
    }
}

// -------- K3: gauss_param = sigmoid(h_last . mixed_w + mixed_b) ------------
__global__ void k_gauss(const float* __restrict__ h,
                        const float* __restrict__ gw,
                        const float* __restrict__ gb,
                        float* __restrict__ out) {
    __shared__ float part[2];
    int b = blockIdx.x, o = blockIdx.y;
    int w = threadIdx.x >> 5, l = threadIdx.x & 31;
    int2 sel = g_sel[b];
    float2 gg = g_gate[b];
    int e = w ? sel.y : sel.x;
    float g = w ? gg.y : gg.x;
    const float* hl = h + ((size_t)b * L_ + (L_ - 1)) * H_;
    const float* wp = gw + ((size_t)e * OUT_ + o) * H_;
    float a = 0.0f;
#pragma unroll 8
    for (int i = l; i < H_; i += 32) a = fmaf(hl[i], wp[i], a);
#pragma unroll
    for (int off = 16; off > 0; off >>= 1)
        a += __shfl_down_sync(0xffffffff, a, off);
    if (l == 0) part[w] = g * (a + gb[e * OUT_ + o]);
    __syncthreads();
    if (threadIdx.x == 0) {
        float val = part[0] + part[1];
        out[b * OUT_ + o] = 1.0f / (1.0f + expf(-val));
    }
}

// -------- K3.5: init comp output with gated bias ---------------------------
__global__ void k_init(const float* __restrict__ comp_b,
                       float* __restrict__ out) {
    int b = blockIdx.x, l = blockIdx.y;
    int2 sel = g_sel[b];
    float2 gg = g_gate[b];
    const float4* c1 = (const float4*)(comp_b + (size_t)sel.x * V_);
    const float4* c2 = (const float4*)(comp_b + (size_t)sel.y * V_);
    float4* o = (float4*)(out + COMP_OFF + ((size_t)b * L_ + l) * V_);
    for (int i = threadIdx.x; i < V_ / 4; i += 256) {
        float4 a = c1[i], d = c2[i], r;
        r.x = gg.x * a.x + gg.y * d.x;
        r.y = gg.x * a.y + gg.y * d.y;
        r.z = gg.x * a.z + gg.y * d.z;
        r.w = gg.x * a.w + gg.y * d.w;
        o[i] = r;
    }
}

// -------- K4: comp via expert-grouped HMMA jobs, 512 threads ---------------
// CTA(job, vtile): one expert's W tile [128v x 1024k] against NB<=4 b's'
// gate-folded h16 (N=64 each). 16 warps as 4(m) x 4(n); warp tile 32v x 16l
// per b => 64 accum regs/thread, 4 warps/SMSP for latency hiding.
template <int NB>
__device__ __forceinline__ void comp_body(const float* __restrict__ comp_w,
                                          float* __restrict__ out,
                                          unsigned sb, int job, int vbase) {
    const int t = threadIdx.x, wid = t >> 5, lane = t & 31;
    const int warp_m = wid >> 2, warp_n = wid & 3;
    const int e = g_job_e[job];

    int jh[NB], jb[NB];
#pragma unroll
    for (int bi = 0; bi < NB; ++bi) {
        jh[bi] = g_job_h[job * 4 + bi];
        jb[bi] = g_job_b[job * 4 + bi];
    }

    float c[NB][2][2][4];
#pragma unroll
    for (int bi = 0; bi < NB; ++bi)
#pragma unroll
        for (int i = 0; i < 2; ++i)
#pragma unroll
            for (int j = 0; j < 2; ++j)
#pragma unroll
                for (int k = 0; k < 4; ++k) c[bi][i][j][k] = 0.0f;

    // ---- prologue: cp.async h(0) for all NB (1 cp16/thread/b) ----
#pragma unroll
    for (int bi = 0; bi < NB; ++bi) {
        const __half* src = g_h16 + (size_t)jh[bi] * L_ * H_;
        int r = t >> 3, cc = t & 7;
        cp16(sb + SM_B(0, bi) + SWZ(r * 128 + cc * 16), src + r * H_ + cc * 8);
    }
    asm volatile("cp.async.commit_group;" ::: "memory");

    const float* We = comp_w + (size_t)e * V_ * H_;
    float4 wreg[4];
#pragma unroll
    for (int j = 0; j < 2; ++j) {
        int tau = t + 512 * j, r = tau >> 3, cc = tau & 7;
        int v = vbase + r; if (v >= V_) v = V_ - 1;
        const float4* p = (const float4*)(We + (size_t)v * H_ + cc * 8);
        wreg[2 * j] = p[0]; wreg[2 * j + 1] = p[1];
    }

    const int a_row = warp_m * 32 + (lane & 7) + ((lane >> 3) & 1) * 8;
    const int a_kb  = ((lane >> 4) & 1) * 16;
    const int b_row = warp_n * 16 + (lane & 7) + ((lane >> 4) & 1) * 8;
    const int b_kb  = ((lane >> 3) & 1) * 16;

    for (int s = 0; s < 16; ++s) {
        const unsigned Ab = sb + ((s & 1) ? SM_A1 : SM_A0);

        asm volatile("cp.async.wait_group 0;" ::: "memory");

        // store W(s) as f16 (other buffer than compute(s-1) reads)
#pragma unroll
        for (int j = 0; j < 2; ++j) {
            int tau = t + 512 * j, r = tau >> 3, cc = tau & 7;
            __half2 h0 = __floats2half2_rn(wreg[2 * j].x,     wreg[2 * j].y);
            __half2 h1 = __floats2half2_rn(wreg[2 * j].z,     wreg[2 * j].w);
            __half2 h2 = __floats2half2_rn(wreg[2 * j + 1].x, wreg[2 * j + 1].y);
            __half2 h3 = __floats2half2_rn(wreg[2 * j + 1].z, wreg[2 * j + 1].w);
            sts128(Ab + SWZ(r * 128 + cc * 16), h2u(h0), h2u(h1), h2u(h2), h2u(h3));
        }

        if (s + 1 < 16) {
            int k0 = (s + 1) * 64;
#pragma unroll
            for (int j = 0; j < 2; ++j) {
                int tau = t + 512 * j, r = tau >> 3, cc = tau & 7;
                int v = vbase + r; if (v >= V_) v = V_ - 1;
                const float4* p = (const float4*)(We + (size_t)v * H_ + k0 + cc * 8);
                wreg[2 * j] = p[0]; wreg[2 * j + 1] = p[1];
            }
        }

        __syncthreads();

        if (s + 1 < 16) {
            int k0 = (s + 1) * 64, buf = (s + 1) & 1;
#pragma unroll
            for (int bi = 0; bi < NB; ++bi) {
                const __half* src = g_h16 + (size_t)jh[bi] * L_ * H_ + k0;
                int r = t >> 3, cc = t & 7;
                cp16(sb + SM_B(buf, bi) + SWZ(r * 128 + cc * 16),
                     src + r * H_ + cc * 8);
            }
            asm volatile("cp.async.commit_group;" ::: "memory");
        }

        // ---- compute: 4 k-steps; A ldm shared across all NB b's ----
#pragma unroll
        for (int ks = 0; ks < 4; ++ks) {
            unsigned a[2][4];
#pragma unroll
            for (int mt = 0; mt < 2; ++mt) {
                unsigned off = (a_row + mt * 16) * 128 + ks * 32 + a_kb;
                ldm_x4(a[mt][0], a[mt][1], a[mt][2], a[mt][3], Ab + SWZ(off));
            }
#pragma unroll
            for (int bi = 0; bi < NB; ++bi) {
                const unsigned Bb = sb + SM_B(s & 1, bi);
                unsigned bf[4];
                {
                    unsigned off = b_row * 128 + ks * 32 + b_kb;
                    ldm_x4(bf[0], bf[1], bf[2], bf[3], Bb + SWZ(off));
                }
#pragma unroll
                for (int mt = 0; mt < 2; ++mt)
#pragma unroll
                    for (int nt = 0; nt < 2; ++nt) {
                        mma16816(c[bi][mt][nt][0], c[bi][mt][nt][1],
                                 c[bi][mt][nt][2], c[bi][mt][nt][3],
                                 a[mt][0], a[mt][1], a[mt][2], a[mt][3],
                                 bf[nt * 2], bf[nt * 2 + 1]);
                    }
            }
        }
    }

    // ---- epilogue: atomicAdd into bias-initialized out ----
    const int lq = lane >> 2, ln = (lane & 3) * 2;
#pragma unroll
    for (int bi = 0; bi < NB; ++bi) {
        float* ob = out + COMP_OFF + (size_t)jb[bi] * L_ * V_;
#pragma unroll
        for (int mt = 0; mt < 2; ++mt) {
            int v0 = vbase + warp_m * 32 + mt * 16 + lq;
            int v1 = v0 + 8;
#pragma unroll
            for (int nt = 0; nt < 2; ++nt) {
                int l0 = warp_n * 16 + nt * 8 + ln;
                if (v0 < V_) {
                    atomicAdd(&ob[(size_t)l0 * V_ + v0],       c[bi][mt][nt][0]);
                    atomicAdd(&ob[(size_t)(l0 + 1) * V_ + v0], c[bi][mt][nt][1]);
                }
                if (v1 < V_) {
                    atomicAdd(&ob[(size_t)l0 * V_ + v1],       c[bi][mt][nt][2]);
                    atomicAdd(&ob[(size_t)(l0 + 1) * V_ + v1], c[bi][mt][nt][3]);
                }
            }
        }
    }
}

__global__ __launch_bounds__(512, 1)
void k_comp_mma(const float* __restrict__ comp_w,
                float* __restrict__ out) {
    const int job = blockIdx.x;
    const int nb = g_job_nb[job];
    if (nb == 0) return;
    extern __shared__ __align__(1024) char smem[];
    const unsigned sb = smem_u32(smem);
    const int vbase = blockIdx.y * 128;
    switch (nb) {
        case 4:  comp_body<4>(comp_w, out, sb, job, vbase); break;
        case 3:  comp_body<3>(comp_w, out, sb, job, vbase); break;
        case 2:  comp_body<2>(comp_w, out, sb, job, vbase); break;
        default: comp_body<1>(comp_w, out, sb, job, vbase); break;
    }
}

// ---------------------------------------------------------------------------
extern "C" void kernel_launch(void* const* d_in, const int* in_sizes, int n_in,
                              void* d_out, int out_size) {
    const float* q      = (const float*)d_in[0];
    const float* h      = (const float*)d_in[1];
    const float* gw1    = (const float*)d_in[2];
    const float* gb1    = (const float*)d_in[3];
    const float* gw2    = (const float*)d_in[4];
    const float* gb2    = (const float*)d_in[5];
    const float* gaussw = (const float*)d_in[6];
    const float* gaussb = (const float*)d_in[7];
    const float* compw  = (const float*)d_in[8];
    const float* compb  = (const float*)d_in[9];
    float* out = (float*)d_out;

    cudaFuncSetAttribute(k_comp_mma, cudaFuncAttributeMaxDynamicSharedMemorySize,
                         SMEM_TOTAL);

    k_hid<<<dim3(B_, 4), 128>>>(q, gw1, gb1);
    k_gate<<<1, 256>>>(gw2, gb2, out);
    k_prep<<<dim3(B_, 2), 256>>>(h);
    k_gauss<<<dim3(B_, OUT_), 64>>>(h, gaussw, gaussb, out);
    k_init<<<dim3(B_, L_), 256>>>(compb, out);
    k_comp_mma<<<dim3(NJOBS, NVT), 512, SMEM_TOTAL>>>(compw, out);
}